// round 6
// baseline (speedup 1.0000x reference)
#include <cuda_runtime.h>

#define BATCH 2
#define NCAM  6
#define CH    128
#define IH    16
#define IW    44
#define ND    64
#define HW    (IH*IW)                 // 704
#define NPTS  (NCAM*ND*IH*IW)         // 270336 geometry points (batch-independent)
#define BEV_H 256
#define BEV_W 256
#define NBIN  (BEV_H*BEV_W)           // 65536
#define NTILE (NBIN/32)               // 2048
#define CAMSTRIDE (NCAM*ND*HW)        // depth elements per batch

#define PT_BLOCKS   (NPTS/256)        // 1056
#define TR_BLOCKS   ((CH/32)*(HW/32)*BATCH*NCAM)  // 4*22*12 = 1056
#define FILL_BLOCKS (NPTS/1024)       // 264

// Static scratch (allocation-free per harness rules)
__device__ float g_featT[(size_t)BATCH*NCAM*HW*CH];  // feat channel-last: (bn, hw, c)
__device__ int   g_bin[NPTS];                        // bin index or -1
__device__ __align__(16) int g_cnt_i[NBIN];          // per-bin count (zeroed at end of each run)
__device__ __align__(16) int g_off[NBIN+1];          // CSR offsets (exclusive)
__device__ __align__(16) int g_wptr[NBIN];           // write cursors for fill
__device__ int   g_bsum[64];
__device__ int   g_boff[64];
__device__ int   g_sched[NTILE];                     // tile schedule, hot first
__device__ int   g_list_fp[NPTS];                    // featT pixel idx: n*HW+hw
__device__ int   g_list_dp[NPTS];                    // depth idx: (n*ND+dci)*HW+hw

// ---------------------------------------------------------------------------
// In-block camera setup: threads 0..5 build Kinv / R / t for their camera in
// shared memory (geometry identical across batch; use b=0 slices).
// ---------------------------------------------------------------------------
__device__ __forceinline__ void cam_setup(const float* __restrict__ intr,
                                          const float* __restrict__ extr,
                                          const int* __restrict__ pimg_h,
                                          const int* __restrict__ pimg_w,
                                          float* sKi, float* sRm, float* stv) {
    int n = threadIdx.x;
    if (n < NCAM) {
        float img_h = (float)pimg_h[0], img_w = (float)pimg_w[0];
        float sx = (float)IW / (img_w / 16.0f);
        float sy = (float)IH / (img_h / 16.0f);
        float rs0 = 16.0f / sx, rs1 = 16.0f / sy, rs2 = 1.0f;

        const float* Kp = intr + n*9;
        float a = Kp[0]*rs0, b = Kp[1]*rs0, c = Kp[2]*rs0;
        float d = Kp[3]*rs1, e = Kp[4]*rs1, f = Kp[5]*rs1;
        float g = Kp[6]*rs2, h = Kp[7]*rs2, i = Kp[8]*rs2;
        float A  = e*i - f*h;
        float Bc = -(d*i - f*g);
        float Cc = d*h - e*g;
        float det = a*A + b*Bc + c*Cc;
        float id = 1.0f / det;
        float* Ki = sKi + n*9;
        Ki[0] = A*id;             Ki[1] = (c*h - b*i)*id;  Ki[2] = (b*f - c*e)*id;
        Ki[3] = Bc*id;            Ki[4] = (a*i - c*g)*id;  Ki[5] = (c*d - a*f)*id;
        Ki[6] = Cc*id;            Ki[7] = (b*g - a*h)*id;  Ki[8] = (a*e - b*d)*id;

        const float* Ep = extr + n*16;
        #pragma unroll
        for (int r = 0; r < 3; r++) {
            #pragma unroll
            for (int cc = 0; cc < 3; cc++) sRm[n*9 + r*3+cc] = Ep[r*4+cc];
            stv[n*3 + r] = Ep[r*4+3];
        }
    }
}

// ---------------------------------------------------------------------------
// Fused kernel A: blocks [0, PT_BLOCKS) do point geometry (bin + count);
// blocks [PT_BLOCKS, PT_BLOCKS+TR_BLOCKS) do the feat transpose.
// ---------------------------------------------------------------------------
__global__ void __launch_bounds__(256) pointA_kernel(
        const float* __restrict__ feat,
        const float* __restrict__ intr, const float* __restrict__ extr,
        const int* __restrict__ pimg_h, const int* __restrict__ pimg_w) {
    if (blockIdx.x < PT_BLOCKS) {
        __shared__ float sKi[NCAM*9], sRm[NCAM*9], stv[NCAM*3];
        cam_setup(intr, extr, pimg_h, pimg_w, sKi, sRm, stv);
        __syncthreads();

        int wp = blockIdx.x * 256 + threadIdx.x;
        int w   = wp % IW;  int t = wp / IW;
        int h   = t % IH;   t /= IH;
        int dci = t % ND;
        int n   = t / ND;

        float dd = 1.0f + (59.0f / 63.0f) * (float)dci;  // linspace(1,60,64)
        float ux = (float)w * dd;
        float vy = (float)h * dd;

        const float* Ki = sKi + n*9;
        float pcx = Ki[0]*ux + Ki[1]*vy + Ki[2]*dd;
        float pcy = Ki[3]*ux + Ki[4]*vy + Ki[5]*dd;
        float pcz = Ki[6]*ux + Ki[7]*vy + Ki[8]*dd;

        const float* Rm = sRm + n*9;
        const float* tv = stv + n*3;
        float px = Rm[0]*pcx + Rm[1]*pcy + Rm[2]*pcz + tv[0];
        float py = Rm[3]*pcx + Rm[4]*pcy + Rm[5]*pcz + tv[1];
        float pz = Rm[6]*pcx + Rm[7]*pcy + Rm[8]*pcz + tv[2];

        int xi = (int)__fdiv_rn(px - (-51.2f), 0.4f);
        int yi = (int)__fdiv_rn(py - (-51.2f), 0.4f);
        bool valid = (xi >= 0) & (xi < BEV_W) & (yi >= 0) & (yi < BEV_H)
                   & (pz >= -5.0f) & (pz <= 3.0f);

        int bin = yi * BEV_W + xi;
        g_bin[wp] = valid ? bin : -1;
        if (valid) atomicAdd(&g_cnt_i[bin], 1);
    } else {
        __shared__ float tile[32][33];
        int tb  = blockIdx.x - PT_BLOCKS;
        int c0  = (tb & 3) * 32;          // CH/32 = 4
        int hw0 = ((tb >> 2) % 22) * 32;  // HW/32 = 22
        int bn  = tb / 88;
        int x = threadIdx.x & 31, y = threadIdx.x >> 5;
        const float* src = feat + (size_t)bn * CH * HW;
        #pragma unroll
        for (int k = 0; k < 4; k++)
            tile[y + k*8][x] = src[(size_t)(c0 + y + k*8) * HW + hw0 + x];
        __syncthreads();
        #pragma unroll
        for (int k = 0; k < 4; k++)
            g_featT[((size_t)bn * HW + hw0 + y + k*8) * CH + c0 + x] = tile[x][y + k*8];
    }
}

// ---------------------------------------------------------------------------
// Parallel scan: 64 blocks x 256 threads x int4, then 64-sum scan, add-back.
// ---------------------------------------------------------------------------
__global__ void scan1_kernel() {
    __shared__ int wsum[8];
    __shared__ int wexcl[8];
    int t  = threadIdx.x;
    int gb = blockIdx.x * 1024 + t * 4;
    int4 c = *(const int4*)&g_cnt_i[gb];
    int s = c.x + c.y + c.z + c.w;
    int lane = t & 31, wid = t >> 5;
    int incl = s;
    #pragma unroll
    for (int d = 1; d < 32; d <<= 1) {
        int v = __shfl_up_sync(0xffffffffu, incl, d);
        if (lane >= d) incl += v;
    }
    if (lane == 31) wsum[wid] = incl;
    __syncthreads();
    if (t < 8) {
        int v = wsum[t];
        int iv = v;
        #pragma unroll
        for (int d = 1; d < 8; d <<= 1) {
            int u = __shfl_up_sync(0xffu, iv, d);
            if (t >= d) iv += u;
        }
        wexcl[t] = iv - v;
    }
    __syncthreads();
    int excl = incl - s + wexcl[wid];
    int4 o;
    o.x = excl; o.y = o.x + c.x; o.z = o.y + c.y; o.w = o.z + c.z;
    *(int4*)&g_off[gb] = o;
    if (t == 255) g_bsum[blockIdx.x] = excl + s;
}

__global__ void scan2_kernel() {
    __shared__ int w0;
    int t = threadIdx.x;                 // 0..63
    int v = g_bsum[t];
    int lane = t & 31, wid = t >> 5;
    int iv = v;
    #pragma unroll
    for (int d = 1; d < 32; d <<= 1) {
        int u = __shfl_up_sync(0xffffffffu, iv, d);
        if (lane >= d) iv += u;
    }
    if (t == 31) w0 = iv;
    __syncthreads();
    int excl = iv - v + (wid ? w0 : 0);
    g_boff[t] = excl;
    if (t == 63) g_off[NBIN] = excl + v;
}

__global__ void scan3_kernel() {
    int t  = threadIdx.x;
    int gb = blockIdx.x * 1024 + t * 4;
    int base = g_boff[blockIdx.x];
    int4 o = *(const int4*)&g_off[gb];
    o.x += base; o.y += base; o.z += base; o.w += base;
    *(int4*)&g_off[gb]  = o;
    *(int4*)&g_wptr[gb] = o;
}

// ---------------------------------------------------------------------------
// Fused kernel B: blocks [0, FILL_BLOCKS) compact points into per-bin lists;
// block FILL_BLOCKS builds the hot-first tile schedule AND re-zeroes g_cnt_i
// for the next graph replay (fill & sched are independent; both post-scan).
// ---------------------------------------------------------------------------
__global__ void __launch_bounds__(1024) fillB_kernel() {
    int t = threadIdx.x;
    if (blockIdx.x < FILL_BLOCKS) {
        int wp = blockIdx.x * 1024 + t;
        int bin = g_bin[wp];
        if (bin < 0) return;

        int w   = wp % IW;  int q = wp / IW;
        int h   = q % IH;   q /= IH;
        int dci = q % ND;
        int n   = q / ND;
        int hw  = h * IW + w;

        int pos = atomicAdd(&g_wptr[bin], 1);
        g_list_fp[pos] = n * HW + hw;
        g_list_dp[pos] = (n * ND + dci) * HW + hw;
    } else {
        // re-zero counts for next run (module init covers the first run)
        int4 z = {0, 0, 0, 0};
        #pragma unroll
        for (int j = 0; j < 16; j++)
            *(int4*)&g_cnt_i[(t * 16 + j) * 4] = z;

        // hot-first schedule over 2048 tiles
        __shared__ int bcnt[8], bbase[8];
        if (t < 8) bcnt[t] = 0;
        __syncthreads();
        int ks[2];
        #pragma unroll
        for (int j = 0; j < 2; j++) {
            int tile = t + j * 1024;
            int cnt = g_off[tile*32 + 32] - g_off[tile*32];
            int k = cnt > 4096 ? 0 : cnt > 2048 ? 1 : cnt > 1024 ? 2 : cnt > 512 ? 3 :
                    cnt > 256  ? 4 : cnt > 128  ? 5 : cnt > 64   ? 6 : 7;
            ks[j] = k;
            atomicAdd(&bcnt[k], 1);
        }
        __syncthreads();
        if (t == 0) {
            int r = 0;
            #pragma unroll
            for (int k = 0; k < 8; k++) { bbase[k] = r; r += bcnt[k]; }
        }
        __syncthreads();
        #pragma unroll
        for (int j = 0; j < 2; j++) {
            int pos = atomicAdd(&bbase[ks[j]], 1);
            g_sched[pos] = t + j * 1024;
        }
    }
}

// ---------------------------------------------------------------------------
// Gather: block = 32-bin tile (hot-first schedule). Bins are split into <=16
// chunks of >=128 points; 16 warps steal chunks from a shared counter,
// accumulate feat4*depth in registers, then atomicAdd partials into the smem
// tile. Write-out: (bin,c)->(c,bin) transpose fused with /(K+1e-5), coalesced.
// ---------------------------------------------------------------------------
#define MAXCHUNK 512
__global__ void __launch_bounds__(512) gather_kernel(const float* __restrict__ depth,
                                                     float* __restrict__ out) {
    __shared__ float acc[BATCH][32][CH + 1];
    __shared__ float scnt[32];
    __shared__ short cbin[MAXCHUNK];
    __shared__ int   cbeg[MAXCHUNK];
    __shared__ short clen[MAXCHUNK];
    __shared__ int   stotal, sctr;

    int tile = g_sched[blockIdx.x];
    int bin0 = tile * 32;
    int tid  = threadIdx.x;
    int warp = tid >> 5;
    int lane = tid & 31;

    // zero accumulators
    float* accf = &acc[0][0][0];
    #pragma unroll
    for (int j = 0; j < (BATCH*32*(CH+1) + 511) / 512; j++) {
        int idx = tid + j * 512;
        if (idx < BATCH*32*(CH+1)) accf[idx] = 0.f;
    }
    if (tid == 0) sctr = 0;

    // warp 0 builds the chunk list
    if (warp == 0) {
        int bin = bin0 + lane;
        int beg = g_off[bin];
        int end = g_off[bin + 1];
        int cnt = end - beg;
        scnt[lane] = (float)cnt;
        int nch = (cnt + 127) >> 7;
        if (nch > 16) nch = 16;
        int cl  = nch ? (cnt + nch - 1) / nch : 0;
        // exclusive prefix of nch across the warp
        int incl = nch;
        #pragma unroll
        for (int d = 1; d < 32; d <<= 1) {
            int v = __shfl_up_sync(0xffffffffu, incl, d);
            if (lane >= d) incl += v;
        }
        int base = incl - nch;
        for (int j = 0; j < nch; j++) {
            int b0 = beg + j * cl;
            cbin[base + j] = (short)lane;
            cbeg[base + j] = b0;
            int l = end - b0; if (l > cl) l = cl;
            clen[base + j] = (short)l;
        }
        if (lane == 31) stotal = incl;
    }
    __syncthreads();

    int total = stotal;
    for (;;) {
        int cidx;
        if (lane == 0) cidx = atomicAdd(&sctr, 1);
        cidx = __shfl_sync(0xffffffffu, cidx, 0);
        if (cidx >= total) break;

        int bl  = cbin[cidx];
        int beg = cbeg[cidx];
        int end = beg + clen[cidx];
        float4 a0 = {0.f, 0.f, 0.f, 0.f};
        float4 a1 = {0.f, 0.f, 0.f, 0.f};
        #pragma unroll 4
        for (int i = beg; i < end; i++) {
            int fpix = g_list_fp[i];
            int dpo  = g_list_dp[i];
            float d0 = __ldg(&depth[dpo]);
            float d1 = __ldg(&depth[CAMSTRIDE + dpo]);
            float4 v0 = *((const float4*)(g_featT + (size_t)fpix * CH) + lane);
            float4 v1 = *((const float4*)(g_featT + ((size_t)(NCAM*HW) + fpix) * CH) + lane);
            a0.x += v0.x * d0;  a0.y += v0.y * d0;  a0.z += v0.z * d0;  a0.w += v0.w * d0;
            a1.x += v1.x * d1;  a1.y += v1.y * d1;  a1.z += v1.z * d1;  a1.w += v1.w * d1;
        }
        int c4 = lane * 4;
        atomicAdd(&acc[0][bl][c4+0], a0.x);  atomicAdd(&acc[0][bl][c4+1], a0.y);
        atomicAdd(&acc[0][bl][c4+2], a0.z);  atomicAdd(&acc[0][bl][c4+3], a0.w);
        atomicAdd(&acc[1][bl][c4+0], a1.x);  atomicAdd(&acc[1][bl][c4+1], a1.y);
        atomicAdd(&acc[1][bl][c4+2], a1.z);  atomicAdd(&acc[1][bl][c4+3], a1.w);
    }
    __syncthreads();

    // 256 output rows (b,c), each 32 consecutive bins -> coalesced 128B stores
    for (int r = warp; r < BATCH * CH; r += 16) {
        int b = r >> 7;
        int c = r & 127;
        float v   = acc[b][lane][c];             // stride-129: conflict-free
        float cnt = scnt[lane] + 1e-5f;
        out[((size_t)(b * CH + c)) * NBIN + bin0 + lane] = __fdiv_rn(v, cnt);
    }
}

extern "C" void kernel_launch(void* const* d_in, const int* in_sizes, int n_in,
                              void* d_out, int out_size) {
    const float* feat  = (const float*)d_in[0];
    const float* depth = (const float*)d_in[1];
    const float* intr  = (const float*)d_in[2];
    const float* extr  = (const float*)d_in[3];
    const int*   img_h = (const int*)d_in[4];
    const int*   img_w = (const int*)d_in[5];
    float* out = (float*)d_out;

    pointA_kernel<<<PT_BLOCKS + TR_BLOCKS, 256>>>(feat, intr, extr, img_h, img_w);
    scan1_kernel<<<64, 256>>>();
    scan2_kernel<<<1, 64>>>();
    scan3_kernel<<<64, 256>>>();
    fillB_kernel<<<FILL_BLOCKS + 1, 1024>>>();
    gather_kernel<<<NTILE, 512>>>(depth, out);
}